// round 15
// baseline (speedup 1.0000x reference)
#include <cuda_runtime.h>
#include <cuda_bf16.h>
#include <cstdint>

// ---- problem constants ----
#define B_    8
#define N1_   8192
#define N2_   2048
#define C1_   128
#define C2_   256
#define INCH  384
#define O1_   256
#define O2_   256

// ---- device scratch ----
__device__ float g_b1eff[O1_], g_b2eff[O2_];
__device__ __align__(16) float g_PT[(size_t)B_ * N2_ * O1_];      // P^T [b][n2][o1]
__device__ int   g_idx[B_ * N1_ * 3];
__device__ float g_wgt[B_ * N1_ * 3];

// A operands in mma-fragment order: [b][rowtile][ktile][lane] -> uint4
__device__ __align__(16) uint4 g_f1P_hi[(size_t)B_ * 512 * 8 * 32], g_f1P_lo[(size_t)B_ * 512 * 8 * 32];
__device__ __align__(16) uint4 g_f2P_hi[(size_t)B_ * 128 * 16 * 32], g_f2P_lo[(size_t)B_ * 128 * 16 * 32];

// fragment-order packed weights
__device__ __align__(16) uint4 g_W2p_hi [8192], g_W2p_lo [8192];
__device__ __align__(16) uint4 g_W1bp_hi[4096], g_W1bp_lo[4096];
__device__ __align__(16) uint4 g_W1ap_hi[8192], g_W1ap_lo[8192];

// ============================================================
// primitives
// ============================================================
__device__ __forceinline__ uint32_t smem_u32(const void* p) {
    uint32_t a;
    asm("{ .reg .u64 t; cvta.to.shared.u64 t, %1; cvt.u32.u64 %0, t; }" : "=r"(a) : "l"(p));
    return a;
}
__device__ __forceinline__ void ldsm4(uint32_t* r, uint32_t addr) {
    asm volatile("ldmatrix.sync.aligned.m8n8.x4.shared.b16 {%0,%1,%2,%3}, [%4];"
                 : "=r"(r[0]), "=r"(r[1]), "=r"(r[2]), "=r"(r[3]) : "r"(addr));
}
__device__ __forceinline__ void mma16816(float* c, const uint32_t* a, uint32_t b0, uint32_t b1) {
    asm volatile(
        "mma.sync.aligned.m16n8k16.row.col.f32.bf16.bf16.f32 "
        "{%0,%1,%2,%3}, {%4,%5,%6,%7}, {%8,%9}, {%0,%1,%2,%3};"
        : "+f"(c[0]), "+f"(c[1]), "+f"(c[2]), "+f"(c[3])
        : "r"(a[0]), "r"(a[1]), "r"(a[2]), "r"(a[3]), "r"(b0), "r"(b1));
}
__device__ __forceinline__ uint32_t splitpack(float a, float b, uint32_t& lo) {
    __nv_bfloat16 ha = __float2bfloat16(a), hb = __float2bfloat16(b);
    __nv_bfloat16 la = __float2bfloat16(a - __bfloat162float(ha));
    __nv_bfloat16 lb = __float2bfloat16(b - __bfloat162float(hb));
    __nv_bfloat162 H2; H2.x = ha; H2.y = hb;
    __nv_bfloat162 L2; L2.x = la; L2.y = lb;
    lo = *(uint32_t*)&L2;
    return *(uint32_t*)&H2;
}
__device__ __forceinline__ uint32_t fold2(float wa, float wb, float scale, uint32_t& lo) {
    return splitpack(wa * scale, wb * scale, lo);
}

// ============================================================
// FUSED gemm1+gemm2 (byte-identical to the R13/R14-measured 117.8us version)
// ============================================================
#define H1P  264
#define OTP  68
#define OF_H1HI 0
#define OF_H1LO 33792
#define OF_OUTT 0
#define FSM_BYTES 69632

__global__ void __launch_bounds__(256, 2) fused12_kernel(float* __restrict__ out) {
    extern __shared__ __align__(16) char fsm[];
    __nv_bfloat16* h1hi = (__nv_bfloat16*)(fsm + OF_H1HI);
    __nv_bfloat16* h1lo = (__nv_bfloat16*)(fsm + OF_H1LO);
    float*         outT = (float*)(fsm + OF_OUTT);

    const int tid = threadIdx.x, lane = tid & 31, wid = tid >> 5;
    const int warpM = wid >> 2, warpN = wid & 3;
    const int b = blockIdx.y;
    const int pt0 = blockIdx.x * 64;

    const uint32_t h1hiB = smem_u32(h1hi), h1loB = smem_u32(h1lo);

    const uint32_t aRowSel = lane & 15;
    const uint32_t aColSel = (lane >> 4) << 3;

    // ---------------- stage 1: sync-free, A fragments from g_f1P ----------------
    float acc[2][8][4];
    #pragma unroll
    for (int i = 0; i < 2; i++)
        #pragma unroll
        for (int j = 0; j < 8; j++)
            #pragma unroll
            for (int k = 0; k < 4; k++) acc[i][j][k] = 0.f;

    const size_t aB1 = (((size_t)b * 512 + blockIdx.x * 4 + warpM * 2) * 8) * 32 + lane;

    for (int kt = 0; kt < 8; kt++) {
        uint4 afh[2], afl[2];
        #pragma unroll
        for (int mi = 0; mi < 2; mi++) {
            afh[mi] = g_f1P_hi[aB1 + mi * 256 + kt * 32];
            afl[mi] = g_f1P_lo[aB1 + mi * 256 + kt * 32];
        }
        uint4 fh[4], fl[4];
        #pragma unroll
        for (int nj = 0; nj < 4; nj++) {
            size_t o = (((size_t)kt * 4 + warpN) * 4 + nj) * 32 + lane;
            fh[nj] = g_W1bp_hi[o];
            fl[nj] = g_W1bp_lo[o];
        }
        #pragma unroll
        for (int nj = 0; nj < 4; nj++) {
            const uint32_t* BH = (const uint32_t*)&fh[nj];
            const uint32_t* BL = (const uint32_t*)&fl[nj];
            #pragma unroll
            for (int mi = 0; mi < 2; mi++) {
                const uint32_t* AH = (const uint32_t*)&afh[mi];
                const uint32_t* AL = (const uint32_t*)&afl[mi];
                #pragma unroll
                for (int sub = 0; sub < 2; sub++) {
                    int ni = nj * 2 + sub;
                    uint32_t b0 = BH[sub * 2], b1 = BH[sub * 2 + 1];
                    uint32_t c0_ = BL[sub * 2], c1_ = BL[sub * 2 + 1];
                    mma16816(acc[mi][ni], AH, b0, b1);
                    mma16816(acc[mi][ni], AH, c0_, c1_);
                    mma16816(acc[mi][ni], AL, b0, b1);
                }
            }
        }
    }

    // ---------------- epilogue 1: gather + bias + relu -> h1 smem ----------------
    {
        const int r0 = lane >> 2;
        const int c0 = (lane & 3) * 2;
        const int*   IX = g_idx + (size_t)b * N1_ * 3;
        const float* WG = g_wgt + (size_t)b * N1_ * 3;
        const float* PT = g_PT + (size_t)b * N2_ * O1_;
        #pragma unroll
        for (int mi = 0; mi < 2; mi++)
            #pragma unroll
            for (int h = 0; h < 2; h++) {
                int gmL = warpM * 32 + mi * 16 + r0 + h * 8;
                int n = pt0 + gmL;
                int i0 = IX[n * 3], i1 = IX[n * 3 + 1], i2 = IX[n * 3 + 2];
                float w0 = WG[n * 3], w1 = WG[n * 3 + 1], w2 = WG[n * 3 + 2];
                #pragma unroll
                for (int ni = 0; ni < 8; ni++) {
                    int gn = warpN * 64 + ni * 8 + c0;
                    float2 p0 = *(const float2*)&PT[(size_t)i0 * O1_ + gn];
                    float2 p1 = *(const float2*)&PT[(size_t)i1 * O1_ + gn];
                    float2 p2 = *(const float2*)&PT[(size_t)i2 * O1_ + gn];
                    float2 bs = *(const float2*)&g_b1eff[gn];
                    float v0 = acc[mi][ni][h * 2 + 0] + bs.x + w0 * p0.x + w1 * p1.x + w2 * p2.x;
                    float v1 = acc[mi][ni][h * 2 + 1] + bs.y + w0 * p0.y + w1 * p1.y + w2 * p2.y;
                    v0 = fmaxf(v0, 0.f); v1 = fmaxf(v1, 0.f);
                    uint32_t lo, hi = splitpack(v0, v1, lo);
                    *(uint32_t*)&h1hi[gmL * H1P + gn] = hi;
                    *(uint32_t*)&h1lo[gmL * H1P + gn] = lo;
                }
            }
    }
    __syncthreads();

    // ---------------- stage 2: no syncs ----------------
    float acc2[2][8][4];
    #pragma unroll
    for (int i = 0; i < 2; i++)
        #pragma unroll
        for (int j = 0; j < 8; j++)
            #pragma unroll
            for (int k = 0; k < 4; k++) acc2[i][j][k] = 0.f;

    for (int kc = 0; kc < 8; kc++) {
        #pragma unroll
        for (int ks = 0; ks < 2; ks++) {
            uint4 fh[4], fl[4];
            #pragma unroll
            for (int nj = 0; nj < 4; nj++) {
                size_t o = ((((size_t)kc * 2 + ks) * 4 + warpN) * 4 + nj) * 32 + lane;
                fh[nj] = g_W2p_hi[o];
                fl[nj] = g_W2p_lo[o];
            }
            uint32_t ah[2][4], al[2][4];
            #pragma unroll
            for (int mi = 0; mi < 2; mi++) {
                uint32_t off = ((warpM * 32 + mi * 16 + aRowSel) * H1P + kc * 32 + ks * 16 + aColSel) * 2;
                ldsm4(ah[mi], h1hiB + off);
                ldsm4(al[mi], h1loB + off);
            }
            #pragma unroll
            for (int nj = 0; nj < 4; nj++) {
                const uint32_t* BH = (const uint32_t*)&fh[nj];
                const uint32_t* BL = (const uint32_t*)&fl[nj];
                #pragma unroll
                for (int mi = 0; mi < 2; mi++)
                    #pragma unroll
                    for (int sub = 0; sub < 2; sub++) {
                        int ni = nj * 2 + sub;
                        uint32_t b0 = BH[sub * 2], b1 = BH[sub * 2 + 1];
                        uint32_t c0_ = BL[sub * 2], c1_ = BL[sub * 2 + 1];
                        mma16816(acc2[mi][ni], ah[mi], b0, b1);
                        mma16816(acc2[mi][ni], ah[mi], c0_, c1_);
                        mma16816(acc2[mi][ni], al[mi], b0, b1);
                    }
            }
        }
    }
    __syncthreads();

    // ---------------- epilogue 2 ----------------
    {
        const int r0 = lane >> 2;
        const int c0 = (lane & 3) * 2;
        #pragma unroll
        for (int mi = 0; mi < 2; mi++)
            #pragma unroll
            for (int h = 0; h < 2; h++) {
                int gmL = warpM * 32 + mi * 16 + r0 + h * 8;
                #pragma unroll
                for (int ni = 0; ni < 8; ni++) {
                    int gn = warpN * 64 + ni * 8 + c0;
                    float2 bs = *(const float2*)&g_b2eff[gn];
                    outT[(size_t)gn * OTP + gmL]       = fmaxf(acc2[mi][ni][h * 2 + 0] + bs.x, 0.f);
                    outT[(size_t)(gn + 1) * OTP + gmL] = fmaxf(acc2[mi][ni][h * 2 + 1] + bs.y, 0.f);
                }
            }
    }
    __syncthreads();

    float* dst = out + (size_t)b * O2_ * N1_ + pt0;
    for (int i = tid; i < 256 * 16; i += 256) {
        int o2 = i >> 4;
        int c = (i & 15) << 2;
        uint4 v = *(uint4*)&outT[o2 * OTP + c];
        *(uint4*)(dst + (size_t)o2 * N1_ + c) = v;
    }
}

// ============================================================
// gemmP v3 (R13/R14 body, standalone): zero smem, zero syncs.
// ============================================================
__global__ void __launch_bounds__(256, 2) gemmP_kernel() {
    const int tid = threadIdx.x, lane = tid & 31, wid = tid >> 5;
    const int warpM = wid >> 2, warpN = wid & 3;
    const int b = blockIdx.z;
    const int Mbase = blockIdx.x * 64;
    const int nb = blockIdx.y;

    float acc[2][4][4];
    #pragma unroll
    for (int i = 0; i < 2; i++)
        #pragma unroll
        for (int j = 0; j < 4; j++)
            #pragma unroll
            for (int k = 0; k < 4; k++) acc[i][j][k] = 0.f;

    const size_t aB = (((size_t)b * 128 + (Mbase >> 4) + warpM * 2) * 16) * 32 + lane;

    for (int kt = 0; kt < 16; kt++) {
        uint4 afh[2], afl[2];
        #pragma unroll
        for (int mi = 0; mi < 2; mi++) {
            afh[mi] = g_f2P_hi[aB + mi * 512 + kt * 32];
            afl[mi] = g_f2P_lo[aB + mi * 512 + kt * 32];
        }
        uint4 fh[2], fl[2];
        #pragma unroll
        for (int nj = 0; nj < 2; nj++) {
            size_t o = (((size_t)(nb * 16 + kt) * 4 + warpN) * 2 + nj) * 32 + lane;
            fh[nj] = g_W1ap_hi[o];
            fl[nj] = g_W1ap_lo[o];
        }
        #pragma unroll
        for (int nj = 0; nj < 2; nj++) {
            const uint32_t* BH = (const uint32_t*)&fh[nj];
            const uint32_t* BL = (const uint32_t*)&fl[nj];
            #pragma unroll
            for (int mi = 0; mi < 2; mi++) {
                const uint32_t* AH = (const uint32_t*)&afh[mi];
                const uint32_t* AL = (const uint32_t*)&afl[mi];
                #pragma unroll
                for (int sub = 0; sub < 2; sub++) {
                    int ni = nj * 2 + sub;
                    uint32_t b0 = BH[sub * 2], b1 = BH[sub * 2 + 1];
                    uint32_t c0_ = BL[sub * 2], c1_ = BL[sub * 2 + 1];
                    mma16816(acc[mi][ni], AH, b0, b1);
                    mma16816(acc[mi][ni], AH, c0_, c1_);
                    mma16816(acc[mi][ni], AL, b0, b1);
                }
            }
        }
    }

    const int r0 = lane >> 2;
    const int c0 = (lane & 3) * 2;
    float* outP = g_PT + (size_t)b * N2_ * O1_;
    const int Nbase = nb * 128;
    #pragma unroll
    for (int mi = 0; mi < 2; mi++)
        #pragma unroll
        for (int h = 0; h < 2; h++) {
            int gm = Mbase + warpM * 32 + mi * 16 + r0 + h * 8;
            #pragma unroll
            for (int ni = 0; ni < 4; ni++) {
                int gn = Nbase + warpN * 32 + ni * 8 + c0;
                *(float2*)&outP[(size_t)gm * O1_ + gn] =
                    make_float2(acc[mi][ni][h * 2], acc[mi][ni][h * 2 + 1]);
            }
        }
}

// ============================================================
// LIGHT kernel: knn (blocks first) + tsplit1 + tsplit2 + weight pack.
// All independent; one shared 32KB smem buffer (union).
// No MMA code -> low registers -> good occupancy for all parts.
// ============================================================
#define L_KNN  256                                   // (N1/256)*B
#define TS1_BLKS  ((N1_ / 32) * (C1_ / 32) * B_)     // 8192
#define TS2_BLKS  ((N2_ / 32) * (C2_ / 32) * B_)     // 4096
#define PACK_BLKS 64
#define RS_ 0.99999500003749969f

__device__ __forceinline__ void tsplit_pack(int n_t, int c_t, int b,
                                            const float* __restrict__ src,
                                            uint4* __restrict__ phi, uint4* __restrict__ plo,
                                            int C, int Np, float (*t)[33]) {
    int n0 = n_t * 32, c0 = c_t * 32;
    int tx = threadIdx.x & 31, ty = threadIdx.x >> 5;
    #pragma unroll
    for (int r = 0; r < 4; r++) {
        int c = c0 + ty + r * 8;
        t[ty + r * 8][tx] = src[((size_t)b * C + c) * Np + n0 + tx];
    }
    __syncthreads();
    int i = threadIdx.x;
    if (i < 128) {
        int tile = i >> 5, lane = i & 31;
        int tn = tile & 1, tc = tile >> 1;
        uint4 h, l;
        uint32_t* hp = (uint32_t*)&h;
        uint32_t* lp = (uint32_t*)&l;
        #pragma unroll
        for (int j = 0; j < 4; j++) {
            int nl = tn * 16 + ((j & 1) << 3) + (lane >> 2);
            int cl = tc * 16 + ((j >> 1) << 3) + (lane & 3) * 2;
            hp[j] = splitpack(t[cl][nl], t[cl + 1][nl], lp[j]);
        }
        int NT = Np / 16, KT = C / 16;
        int rt = n_t * 2 + tn, kt = c_t * 2 + tc;
        size_t o = (((size_t)b * NT + rt) * KT + kt) * 32 + lane;
        phi[o] = h;
        plo[o] = l;
    }
}

__global__ void __launch_bounds__(256) light_kernel(
    const float* __restrict__ xyz1, const float* __restrict__ xyz2,
    const float* __restrict__ feats1, const float* __restrict__ feats2,
    const float* __restrict__ W1, const float* __restrict__ b1,
    const float* __restrict__ g1, const float* __restrict__ be1,
    const float* __restrict__ W2, const float* __restrict__ b2,
    const float* __restrict__ g2, const float* __restrict__ be2) {
    __shared__ __align__(16) char sbuf[32768];   // union: knn float4 cache / tsplit tile
    int bid = blockIdx.x;

    if (bid < L_KNN) {
        // ---------------- kNN (R6/R10-proven body, 1 pt/thread) ----------------
        float4* s2 = (float4*)sbuf;
        int px = bid & 31, b = bid >> 5;
        const float* q = xyz2 + (size_t)b * N2_ * 3;
        for (int i = threadIdx.x; i < N2_; i += 256) {
            float ax = q[i * 3 + 0], ay = q[i * 3 + 1], az = q[i * 3 + 2];
            s2[i] = make_float4(ax, ay, az, ax * ax + ay * ay + az * az);
        }
        __syncthreads();

        int p = px * 256 + threadIdx.x;
        const float* pp = xyz1 + ((size_t)b * N1_ + p) * 3;
        float x = pp[0], y = pp[1], z = pp[2];
        float p2 = x * x + y * y + z * z;

        float d0 = 3.4e38f, d1 = 3.4e38f, d2 = 3.4e38f;
        int   j0 = 0, j1 = 0, j2 = 0;
        #pragma unroll 4
        for (int m = 0; m < N2_; m++) {
            float4 v = s2[m];
            float dot = x * v.x + y * v.y + z * v.z;
            float dd  = (p2 + v.w) - 2.0f * dot;
            if (dd < d2) {
                if (dd < d1) {
                    d2 = d1; j2 = j1;
                    if (dd < d0) { d1 = d0; j1 = j0; d0 = dd; j0 = m; }
                    else         { d1 = dd; j1 = m; }
                } else { d2 = dd; j2 = m; }
            }
        }
        float r0 = sqrtf(fmaxf(d0, 0.f));
        float r1 = sqrtf(fmaxf(d1, 0.f));
        float r2 = sqrtf(fmaxf(d2, 0.f));
        float w0 = 1.0f / fmaxf(r0, 1e-8f);
        float w1 = 1.0f / fmaxf(r1, 1e-8f);
        float w2 = 1.0f / fmaxf(r2, 1e-8f);
        float inv = 1.0f / (w0 + w1 + w2);

        size_t base = ((size_t)b * N1_ + p) * 3;
        g_idx[base + 0] = j0; g_idx[base + 1] = j1; g_idx[base + 2] = j2;
        g_wgt[base + 0] = w0 * inv; g_wgt[base + 1] = w1 * inv; g_wgt[base + 2] = w2 * inv;
        return;
    }
    bid -= L_KNN;

    float (*t)[33] = (float(*)[33])sbuf;
    if (bid < TS1_BLKS) {
        int n_t = bid & 255, c_t = (bid >> 8) & 3, b = bid >> 10;
        tsplit_pack(n_t, c_t, b, feats1, g_f1P_hi, g_f1P_lo, C1_, N1_, t);
        return;
    }
    bid -= TS1_BLKS;
    if (bid < TS2_BLKS) {
        int n_t = bid & 63, c_t = (bid >> 6) & 7, b = bid >> 9;
        tsplit_pack(n_t, c_t, b, feats2, g_f2P_hi, g_f2P_lo, C2_, N2_, t);
        return;
    }
    bid -= TS2_BLKS;

    // ---------------- weight pack + biases ----------------
    int tt = bid * 256 + threadIdx.x;
    int nt = PACK_BLKS * 256;
    for (int i = tt; i < 8192; i += nt) {
        int lane = i & 31, nj = (i >> 5) & 3, wN = (i >> 7) & 3, ks = (i >> 9) & 1, kc = i >> 10;
        int n0 = wN * 64 + nj * 16, k0 = kc * 32 + ks * 16;
        uint4 h, l;
        uint32_t* hp = (uint32_t*)&h;
        uint32_t* lp = (uint32_t*)&l;
        #pragma unroll
        for (int j = 0; j < 4; j++) {
            int n = n0 + ((j >> 1) << 3) + (lane >> 2);
            int k = k0 + ((j & 1) << 3) + (lane & 3) * 2;
            float s = g2[n] * RS_;
            hp[j] = fold2(W2[(size_t)n * O1_ + k], W2[(size_t)n * O1_ + k + 1], s, lp[j]);
        }
        g_W2p_hi[i] = h;
        g_W2p_lo[i] = l;
    }
    for (int i = tt; i < 4096; i += nt) {
        int lane = i & 31, nj = (i >> 5) & 3, wN = (i >> 7) & 3, ks = (i >> 9) & 1, kc = i >> 10;
        int n0 = wN * 64 + nj * 16, k0 = kc * 32 + ks * 16;
        uint4 h, l;
        uint32_t* hp = (uint32_t*)&h;
        uint32_t* lp = (uint32_t*)&l;
        #pragma unroll
        for (int j = 0; j < 4; j++) {
            int n = n0 + ((j >> 1) << 3) + (lane >> 2);
            int k = k0 + ((j & 1) << 3) + (lane & 3) * 2;
            float s = g1[n] * RS_;
            hp[j] = fold2(W1[(size_t)n * INCH + C2_ + k], W1[(size_t)n * INCH + C2_ + k + 1], s, lp[j]);
        }
        g_W1bp_hi[i] = h;
        g_W1bp_lo[i] = l;
    }
    for (int i = tt; i < 8192; i += nt) {
        int lane = i & 31, nj = (i >> 5) & 1, wN = (i >> 6) & 3, ks = (i >> 8) & 1,
            kc = (i >> 9) & 7, nb = (i >> 12) & 1;
        int n0 = nb * 128 + wN * 32 + nj * 16, k0 = kc * 32 + ks * 16;
        uint4 h, l;
        uint32_t* hp = (uint32_t*)&h;
        uint32_t* lp = (uint32_t*)&l;
        #pragma unroll
        for (int j = 0; j < 4; j++) {
            int n = n0 + ((j >> 1) << 3) + (lane >> 2);
            int k = k0 + ((j & 1) << 3) + (lane & 3) * 2;
            float s = g1[n] * RS_;
            hp[j] = fold2(W1[(size_t)n * INCH + k], W1[(size_t)n * INCH + k + 1], s, lp[j]);
        }
        g_W1ap_hi[i] = h;
        g_W1ap_lo[i] = l;
    }
    for (int i = tt; i < O1_; i += nt) g_b1eff[i] = g1[i] * RS_ * b1[i] + be1[i];
    for (int i = tt; i < O2_; i += nt) g_b2eff[i] = g2[i] * RS_ * b2[i] + be2[i];
}

// ============================================================
extern "C" void kernel_launch(void* const* d_in, const int* in_sizes, int n_in,
                              void* d_out, int out_size) {
    const float* xyz1   = (const float*)d_in[0];
    const float* xyz2   = (const float*)d_in[1];
    const float* feats1 = (const float*)d_in[2];
    const float* feats2 = (const float*)d_in[3];
    const float* W1     = (const float*)d_in[4];
    const float* b1     = (const float*)d_in[5];
    const float* g1     = (const float*)d_in[6];
    const float* be1    = (const float*)d_in[7];
    const float* W2     = (const float*)d_in[8];
    const float* b2     = (const float*)d_in[9];
    const float* g2     = (const float*)d_in[10];
    const float* be2    = (const float*)d_in[11];
    float* out = (float*)d_out;

    cudaFuncSetAttribute(fused12_kernel, cudaFuncAttributeMaxDynamicSharedMemorySize, FSM_BYTES);

    light_kernel<<<L_KNN + TS1_BLKS + TS2_BLKS + PACK_BLKS, 256>>>(
        xyz1, xyz2, feats1, feats2, W1, b1, g1, be1, W2, b2, g2, be2);   // idx 0
    gemmP_kernel<<<dim3(N2_ / 64, O1_ / 128, B_), 256>>>();              // idx 1
    fused12_kernel<<<dim3(N1_ / 64, B_), 256, FSM_BYTES>>>(out);         // idx 2
}

// round 16
// speedup vs baseline: 1.0322x; 1.0322x over previous
#include <cuda_runtime.h>
#include <cuda_bf16.h>
#include <cstdint>

// ---- problem constants ----
#define B_    8
#define N1_   8192
#define N2_   2048
#define C1_   128
#define C2_   256
#define INCH  384
#define O1_   256
#define O2_   256
#define SEG   4
#define SEGN  (N2_ / SEG)   // 512

// ---- device scratch ----
__device__ float g_b1eff[O1_], g_b2eff[O2_];
__device__ __align__(16) float g_PT[(size_t)B_ * N2_ * O1_];      // P^T [b][n2][o1]
__device__ int   g_idx[B_ * N1_ * 3];
__device__ float g_wgt[B_ * N1_ * 3];
__device__ float g_pd[(size_t)B_ * SEG * N1_ * 3];                // partial knn dists
__device__ int   g_pj[(size_t)B_ * SEG * N1_ * 3];                // partial knn indices

// A operands in mma-fragment order: [b][rowtile][ktile][lane] -> uint4
__device__ __align__(16) uint4 g_f1P_hi[(size_t)B_ * 512 * 8 * 32], g_f1P_lo[(size_t)B_ * 512 * 8 * 32];
__device__ __align__(16) uint4 g_f2P_hi[(size_t)B_ * 128 * 16 * 32], g_f2P_lo[(size_t)B_ * 128 * 16 * 32];

// fragment-order packed weights
__device__ __align__(16) uint4 g_W2p_hi [8192], g_W2p_lo [8192];
__device__ __align__(16) uint4 g_W1bp_hi[4096], g_W1bp_lo[4096];
__device__ __align__(16) uint4 g_W1ap_hi[8192], g_W1ap_lo[8192];

// ============================================================
// primitives
// ============================================================
__device__ __forceinline__ uint32_t smem_u32(const void* p) {
    uint32_t a;
    asm("{ .reg .u64 t; cvta.to.shared.u64 t, %1; cvt.u32.u64 %0, t; }" : "=r"(a) : "l"(p));
    return a;
}
__device__ __forceinline__ void ldsm4(uint32_t* r, uint32_t addr) {
    asm volatile("ldmatrix.sync.aligned.m8n8.x4.shared.b16 {%0,%1,%2,%3}, [%4];"
                 : "=r"(r[0]), "=r"(r[1]), "=r"(r[2]), "=r"(r[3]) : "r"(addr));
}
__device__ __forceinline__ void mma16816(float* c, const uint32_t* a, uint32_t b0, uint32_t b1) {
    asm volatile(
        "mma.sync.aligned.m16n8k16.row.col.f32.bf16.bf16.f32 "
        "{%0,%1,%2,%3}, {%4,%5,%6,%7}, {%8,%9}, {%0,%1,%2,%3};"
        : "+f"(c[0]), "+f"(c[1]), "+f"(c[2]), "+f"(c[3])
        : "r"(a[0]), "r"(a[1]), "r"(a[2]), "r"(a[3]), "r"(b0), "r"(b1));
}
__device__ __forceinline__ uint32_t splitpack(float a, float b, uint32_t& lo) {
    __nv_bfloat16 ha = __float2bfloat16(a), hb = __float2bfloat16(b);
    __nv_bfloat16 la = __float2bfloat16(a - __bfloat162float(ha));
    __nv_bfloat16 lb = __float2bfloat16(b - __bfloat162float(hb));
    __nv_bfloat162 H2; H2.x = ha; H2.y = hb;
    __nv_bfloat162 L2; L2.x = la; L2.y = lb;
    lo = *(uint32_t*)&L2;
    return *(uint32_t*)&H2;
}
__device__ __forceinline__ uint32_t fold2(float wa, float wb, float scale, uint32_t& lo) {
    return splitpack(wa * scale, wb * scale, lo);
}
__device__ __forceinline__ void knn3_insert(float dd, int m,
                                            float& d0, float& d1, float& d2,
                                            int& j0, int& j1, int& j2) {
    if (dd < d2) {
        if (dd < d1) {
            d2 = d1; j2 = j1;
            if (dd < d0) { d1 = d0; j1 = j0; d0 = dd; j0 = m; }
            else         { d1 = dd; j1 = m; }
        } else { d2 = dd; j2 = m; }
    }
}

// ============================================================
// FUSED gemm1+gemm2 (byte-identical to the R13/R14-measured 117.8us version)
// ============================================================
#define H1P  264
#define OTP  68
#define OF_H1HI 0
#define OF_H1LO 33792
#define OF_OUTT 0
#define FSM_BYTES 69632

__global__ void __launch_bounds__(256, 2) fused12_kernel(float* __restrict__ out) {
    extern __shared__ __align__(16) char fsm[];
    __nv_bfloat16* h1hi = (__nv_bfloat16*)(fsm + OF_H1HI);
    __nv_bfloat16* h1lo = (__nv_bfloat16*)(fsm + OF_H1LO);
    float*         outT = (float*)(fsm + OF_OUTT);

    const int tid = threadIdx.x, lane = tid & 31, wid = tid >> 5;
    const int warpM = wid >> 2, warpN = wid & 3;
    const int b = blockIdx.y;
    const int pt0 = blockIdx.x * 64;

    const uint32_t h1hiB = smem_u32(h1hi), h1loB = smem_u32(h1lo);

    const uint32_t aRowSel = lane & 15;
    const uint32_t aColSel = (lane >> 4) << 3;

    // ---------------- stage 1: sync-free, A fragments from g_f1P ----------------
    float acc[2][8][4];
    #pragma unroll
    for (int i = 0; i < 2; i++)
        #pragma unroll
        for (int j = 0; j < 8; j++)
            #pragma unroll
            for (int k = 0; k < 4; k++) acc[i][j][k] = 0.f;

    const size_t aB1 = (((size_t)b * 512 + blockIdx.x * 4 + warpM * 2) * 8) * 32 + lane;

    for (int kt = 0; kt < 8; kt++) {
        uint4 afh[2], afl[2];
        #pragma unroll
        for (int mi = 0; mi < 2; mi++) {
            afh[mi] = g_f1P_hi[aB1 + mi * 256 + kt * 32];
            afl[mi] = g_f1P_lo[aB1 + mi * 256 + kt * 32];
        }
        uint4 fh[4], fl[4];
        #pragma unroll
        for (int nj = 0; nj < 4; nj++) {
            size_t o = (((size_t)kt * 4 + warpN) * 4 + nj) * 32 + lane;
            fh[nj] = g_W1bp_hi[o];
            fl[nj] = g_W1bp_lo[o];
        }
        #pragma unroll
        for (int nj = 0; nj < 4; nj++) {
            const uint32_t* BH = (const uint32_t*)&fh[nj];
            const uint32_t* BL = (const uint32_t*)&fl[nj];
            #pragma unroll
            for (int mi = 0; mi < 2; mi++) {
                const uint32_t* AH = (const uint32_t*)&afh[mi];
                const uint32_t* AL = (const uint32_t*)&afl[mi];
                #pragma unroll
                for (int sub = 0; sub < 2; sub++) {
                    int ni = nj * 2 + sub;
                    uint32_t b0 = BH[sub * 2], b1 = BH[sub * 2 + 1];
                    uint32_t c0_ = BL[sub * 2], c1_ = BL[sub * 2 + 1];
                    mma16816(acc[mi][ni], AH, b0, b1);
                    mma16816(acc[mi][ni], AH, c0_, c1_);
                    mma16816(acc[mi][ni], AL, b0, b1);
                }
            }
        }
    }

    // ---------------- epilogue 1: gather + bias + relu -> h1 smem ----------------
    {
        const int r0 = lane >> 2;
        const int c0 = (lane & 3) * 2;
        const int*   IX = g_idx + (size_t)b * N1_ * 3;
        const float* WG = g_wgt + (size_t)b * N1_ * 3;
        const float* PT = g_PT + (size_t)b * N2_ * O1_;
        #pragma unroll
        for (int mi = 0; mi < 2; mi++)
            #pragma unroll
            for (int h = 0; h < 2; h++) {
                int gmL = warpM * 32 + mi * 16 + r0 + h * 8;
                int n = pt0 + gmL;
                int i0 = IX[n * 3], i1 = IX[n * 3 + 1], i2 = IX[n * 3 + 2];
                float w0 = WG[n * 3], w1 = WG[n * 3 + 1], w2 = WG[n * 3 + 2];
                #pragma unroll
                for (int ni = 0; ni < 8; ni++) {
                    int gn = warpN * 64 + ni * 8 + c0;
                    float2 p0 = *(const float2*)&PT[(size_t)i0 * O1_ + gn];
                    float2 p1 = *(const float2*)&PT[(size_t)i1 * O1_ + gn];
                    float2 p2 = *(const float2*)&PT[(size_t)i2 * O1_ + gn];
                    float2 bs = *(const float2*)&g_b1eff[gn];
                    float v0 = acc[mi][ni][h * 2 + 0] + bs.x + w0 * p0.x + w1 * p1.x + w2 * p2.x;
                    float v1 = acc[mi][ni][h * 2 + 1] + bs.y + w0 * p0.y + w1 * p1.y + w2 * p2.y;
                    v0 = fmaxf(v0, 0.f); v1 = fmaxf(v1, 0.f);
                    uint32_t lo, hi = splitpack(v0, v1, lo);
                    *(uint32_t*)&h1hi[gmL * H1P + gn] = hi;
                    *(uint32_t*)&h1lo[gmL * H1P + gn] = lo;
                }
            }
    }
    __syncthreads();

    // ---------------- stage 2: no syncs ----------------
    float acc2[2][8][4];
    #pragma unroll
    for (int i = 0; i < 2; i++)
        #pragma unroll
        for (int j = 0; j < 8; j++)
            #pragma unroll
            for (int k = 0; k < 4; k++) acc2[i][j][k] = 0.f;

    for (int kc = 0; kc < 8; kc++) {
        #pragma unroll
        for (int ks = 0; ks < 2; ks++) {
            uint4 fh[4], fl[4];
            #pragma unroll
            for (int nj = 0; nj < 4; nj++) {
                size_t o = ((((size_t)kc * 2 + ks) * 4 + warpN) * 4 + nj) * 32 + lane;
                fh[nj] = g_W2p_hi[o];
                fl[nj] = g_W2p_lo[o];
            }
            uint32_t ah[2][4], al[2][4];
            #pragma unroll
            for (int mi = 0; mi < 2; mi++) {
                uint32_t off = ((warpM * 32 + mi * 16 + aRowSel) * H1P + kc * 32 + ks * 16 + aColSel) * 2;
                ldsm4(ah[mi], h1hiB + off);
                ldsm4(al[mi], h1loB + off);
            }
            #pragma unroll
            for (int nj = 0; nj < 4; nj++) {
                const uint32_t* BH = (const uint32_t*)&fh[nj];
                const uint32_t* BL = (const uint32_t*)&fl[nj];
                #pragma unroll
                for (int mi = 0; mi < 2; mi++)
                    #pragma unroll
                    for (int sub = 0; sub < 2; sub++) {
                        int ni = nj * 2 + sub;
                        uint32_t b0 = BH[sub * 2], b1 = BH[sub * 2 + 1];
                        uint32_t c0_ = BL[sub * 2], c1_ = BL[sub * 2 + 1];
                        mma16816(acc2[mi][ni], ah[mi], b0, b1);
                        mma16816(acc2[mi][ni], ah[mi], c0_, c1_);
                        mma16816(acc2[mi][ni], al[mi], b0, b1);
                    }
            }
        }
    }
    __syncthreads();

    // ---------------- epilogue 2 ----------------
    {
        const int r0 = lane >> 2;
        const int c0 = (lane & 3) * 2;
        #pragma unroll
        for (int mi = 0; mi < 2; mi++)
            #pragma unroll
            for (int h = 0; h < 2; h++) {
                int gmL = warpM * 32 + mi * 16 + r0 + h * 8;
                #pragma unroll
                for (int ni = 0; ni < 8; ni++) {
                    int gn = warpN * 64 + ni * 8 + c0;
                    float2 bs = *(const float2*)&g_b2eff[gn];
                    outT[(size_t)gn * OTP + gmL]       = fmaxf(acc2[mi][ni][h * 2 + 0] + bs.x, 0.f);
                    outT[(size_t)(gn + 1) * OTP + gmL] = fmaxf(acc2[mi][ni][h * 2 + 1] + bs.y, 0.f);
                }
            }
    }
    __syncthreads();

    float* dst = out + (size_t)b * O2_ * N1_ + pt0;
    for (int i = tid; i < 256 * 16; i += 256) {
        int o2 = i >> 4;
        int c = (i & 15) << 2;
        uint4 v = *(uint4*)&outT[o2 * OTP + c];
        *(uint4*)(dst + (size_t)o2 * N1_ + c) = v;
    }
}

// ============================================================
// gemmP v3 (R13/R14 body): zero smem, zero syncs.
// ============================================================
__global__ void __launch_bounds__(256, 2) gemmP_kernel() {
    const int tid = threadIdx.x, lane = tid & 31, wid = tid >> 5;
    const int warpM = wid >> 2, warpN = wid & 3;
    const int b = blockIdx.z;
    const int Mbase = blockIdx.x * 64;
    const int nb = blockIdx.y;

    float acc[2][4][4];
    #pragma unroll
    for (int i = 0; i < 2; i++)
        #pragma unroll
        for (int j = 0; j < 4; j++)
            #pragma unroll
            for (int k = 0; k < 4; k++) acc[i][j][k] = 0.f;

    const size_t aB = (((size_t)b * 128 + (Mbase >> 4) + warpM * 2) * 16) * 32 + lane;

    for (int kt = 0; kt < 16; kt++) {
        uint4 afh[2], afl[2];
        #pragma unroll
        for (int mi = 0; mi < 2; mi++) {
            afh[mi] = g_f2P_hi[aB + mi * 512 + kt * 32];
            afl[mi] = g_f2P_lo[aB + mi * 512 + kt * 32];
        }
        uint4 fh[2], fl[2];
        #pragma unroll
        for (int nj = 0; nj < 2; nj++) {
            size_t o = (((size_t)(nb * 16 + kt) * 4 + warpN) * 2 + nj) * 32 + lane;
            fh[nj] = g_W1ap_hi[o];
            fl[nj] = g_W1ap_lo[o];
        }
        #pragma unroll
        for (int nj = 0; nj < 2; nj++) {
            const uint32_t* BH = (const uint32_t*)&fh[nj];
            const uint32_t* BL = (const uint32_t*)&fl[nj];
            #pragma unroll
            for (int mi = 0; mi < 2; mi++) {
                const uint32_t* AH = (const uint32_t*)&afh[mi];
                const uint32_t* AL = (const uint32_t*)&afl[mi];
                #pragma unroll
                for (int sub = 0; sub < 2; sub++) {
                    int ni = nj * 2 + sub;
                    uint32_t b0 = BH[sub * 2], b1 = BH[sub * 2 + 1];
                    uint32_t c0_ = BL[sub * 2], c1_ = BL[sub * 2 + 1];
                    mma16816(acc[mi][ni], AH, b0, b1);
                    mma16816(acc[mi][ni], AH, c0_, c1_);
                    mma16816(acc[mi][ni], AL, b0, b1);
                }
            }
        }
    }

    const int r0 = lane >> 2;
    const int c0 = (lane & 3) * 2;
    float* outP = g_PT + (size_t)b * N2_ * O1_;
    const int Nbase = nb * 128;
    #pragma unroll
    for (int mi = 0; mi < 2; mi++)
        #pragma unroll
        for (int h = 0; h < 2; h++) {
            int gm = Mbase + warpM * 32 + mi * 16 + r0 + h * 8;
            #pragma unroll
            for (int ni = 0; ni < 4; ni++) {
                int gn = Nbase + warpN * 32 + ni * 8 + c0;
                *(float2*)&outP[(size_t)gm * O1_ + gn] =
                    make_float2(acc[mi][ni][h * 2], acc[mi][ni][h * 2 + 1]);
            }
        }
}

// ============================================================
// SEGMENTED kNN: grid (32, SEG, B). Each block scans 512 candidates
// for 256 query points; 8KB smem; writes partial top-3 (global j).
// ============================================================
__global__ void __launch_bounds__(256) knnseg_kernel(const float* __restrict__ xyz1,
                                                     const float* __restrict__ xyz2) {
    __shared__ __align__(16) float4 s2[SEGN];   // 8KB
    const int px = blockIdx.x, seg = blockIdx.y, b = blockIdx.z;
    const int jbase = seg * SEGN;

    const float* q = xyz2 + ((size_t)b * N2_ + jbase) * 3;
    for (int i = threadIdx.x; i < SEGN; i += 256) {
        float ax = q[i * 3 + 0], ay = q[i * 3 + 1], az = q[i * 3 + 2];
        s2[i] = make_float4(ax, ay, az, ax * ax + ay * ay + az * az);
    }
    __syncthreads();

    int p = px * 256 + threadIdx.x;
    const float* pp = xyz1 + ((size_t)b * N1_ + p) * 3;
    float x = pp[0], y = pp[1], z = pp[2];
    float p2 = x * x + y * y + z * z;

    float d0 = 3.4e38f, d1 = 3.4e38f, d2 = 3.4e38f;
    int   j0 = 0, j1 = 0, j2 = 0;
    #pragma unroll 4
    for (int m = 0; m < SEGN; m++) {
        float4 v = s2[m];
        float dot = x * v.x + y * v.y + z * v.z;
        float dd  = (p2 + v.w) - 2.0f * dot;
        knn3_insert(dd, jbase + m, d0, d1, d2, j0, j1, j2);
    }

    size_t base = (((size_t)b * SEG + seg) * N1_ + p) * 3;
    g_pd[base + 0] = d0; g_pd[base + 1] = d1; g_pd[base + 2] = d2;
    g_pj[base + 0] = j0; g_pj[base + 1] = j1; g_pj[base + 2] = j2;
}

// merge 4 partial top-3s -> final idx/weights.
// Insert in segment order: ties keep earlier arrival = lower j (exact
// reproduction of ascending-j scan semantics).
__global__ void __launch_bounds__(256) knnmerge_kernel() {
    int p = blockIdx.x * 256 + threadIdx.x;      // 0 .. B*N1-1
    int b = p >> 13;                              // N1 = 8192
    int n = p & (N1_ - 1);

    float d0 = 3.4e38f, d1 = 3.4e38f, d2 = 3.4e38f;
    int   j0 = 0, j1 = 0, j2 = 0;
    #pragma unroll
    for (int s = 0; s < SEG; s++) {
        size_t base = (((size_t)b * SEG + s) * N1_ + n) * 3;
        #pragma unroll
        for (int k = 0; k < 3; k++) {
            float dd = g_pd[base + k];
            int   jj = g_pj[base + k];
            knn3_insert(dd, jj, d0, d1, d2, j0, j1, j2);
        }
    }

    float r0 = sqrtf(fmaxf(d0, 0.f));
    float r1 = sqrtf(fmaxf(d1, 0.f));
    float r2 = sqrtf(fmaxf(d2, 0.f));
    float w0 = 1.0f / fmaxf(r0, 1e-8f);
    float w1 = 1.0f / fmaxf(r1, 1e-8f);
    float w2 = 1.0f / fmaxf(r2, 1e-8f);
    float inv = 1.0f / (w0 + w1 + w2);

    size_t base = ((size_t)b * N1_ + n) * 3;
    g_idx[base + 0] = j0; g_idx[base + 1] = j1; g_idx[base + 2] = j2;
    g_wgt[base + 0] = w0 * inv; g_wgt[base + 1] = w1 * inv; g_wgt[base + 2] = w2 * inv;
}

// ============================================================
// prepsplit (R13/R14 measured body): feats -> A-fragment pack; weights pack
// ============================================================
#define TS1_BLKS  ((N1_ / 32) * (C1_ / 32) * B_)      // 8192
#define TS2_BLKS  ((N2_ / 32) * (C2_ / 32) * B_)      // 4096
#define PACK_BLKS 64
#define RS_ 0.99999500003749969f

__device__ __forceinline__ void tsplit_pack(int n_t, int c_t, int b,
                                            const float* __restrict__ src,
                                            uint4* __restrict__ phi, uint4* __restrict__ plo,
                                            int C, int Np, float (*t)[33]) {
    int n0 = n_t * 32, c0 = c_t * 32;
    int tx = threadIdx.x & 31, ty = threadIdx.x >> 5;
    #pragma unroll
    for (int r = 0; r < 4; r++) {
        int c = c0 + ty + r * 8;
        t[ty + r * 8][tx] = src[((size_t)b * C + c) * Np + n0 + tx];
    }
    __syncthreads();
    int i = threadIdx.x;
    if (i < 128) {
        int tile = i >> 5, lane = i & 31;
        int tn = tile & 1, tc = tile >> 1;
        uint4 h, l;
        uint32_t* hp = (uint32_t*)&h;
        uint32_t* lp = (uint32_t*)&l;
        #pragma unroll
        for (int j = 0; j < 4; j++) {
            int nl = tn * 16 + ((j & 1) << 3) + (lane >> 2);
            int cl = tc * 16 + ((j >> 1) << 3) + (lane & 3) * 2;
            hp[j] = splitpack(t[cl][nl], t[cl + 1][nl], lp[j]);
        }
        int NT = Np / 16, KT = C / 16;
        int rt = n_t * 2 + tn, kt = c_t * 2 + tc;
        size_t o = (((size_t)b * NT + rt) * KT + kt) * 32 + lane;
        phi[o] = h;
        plo[o] = l;
    }
}

__global__ void __launch_bounds__(256) prepsplit_kernel(
    const float* __restrict__ feats1, const float* __restrict__ feats2,
    const float* __restrict__ W1, const float* __restrict__ b1,
    const float* __restrict__ g1, const float* __restrict__ be1,
    const float* __restrict__ W2, const float* __restrict__ b2,
    const float* __restrict__ g2, const float* __restrict__ be2) {
    __shared__ float t[32][33];
    int bid = blockIdx.x;
    if (bid < TS1_BLKS) {
        int n_t = bid & 255, c_t = (bid >> 8) & 3, b = bid >> 10;
        tsplit_pack(n_t, c_t, b, feats1, g_f1P_hi, g_f1P_lo, C1_, N1_, t);
        return;
    }
    bid -= TS1_BLKS;
    if (bid < TS2_BLKS) {
        int n_t = bid & 63, c_t = (bid >> 6) & 7, b = bid >> 9;
        tsplit_pack(n_t, c_t, b, feats2, g_f2P_hi, g_f2P_lo, C2_, N2_, t);
        return;
    }
    bid -= TS2_BLKS;
    int tt = bid * 256 + threadIdx.x;
    int nt = PACK_BLKS * 256;
    for (int i = tt; i < 8192; i += nt) {
        int lane = i & 31, nj = (i >> 5) & 3, wN = (i >> 7) & 3, ks = (i >> 9) & 1, kc = i >> 10;
        int n0 = wN * 64 + nj * 16, k0 = kc * 32 + ks * 16;
        uint4 h, l;
        uint32_t* hp = (uint32_t*)&h;
        uint32_t* lp = (uint32_t*)&l;
        #pragma unroll
        for (int j = 0; j < 4; j++) {
            int n = n0 + ((j >> 1) << 3) + (lane >> 2);
            int k = k0 + ((j & 1) << 3) + (lane & 3) * 2;
            float s = g2[n] * RS_;
            hp[j] = fold2(W2[(size_t)n * O1_ + k], W2[(size_t)n * O1_ + k + 1], s, lp[j]);
        }
        g_W2p_hi[i] = h;
        g_W2p_lo[i] = l;
    }
    for (int i = tt; i < 4096; i += nt) {
        int lane = i & 31, nj = (i >> 5) & 3, wN = (i >> 7) & 3, ks = (i >> 9) & 1, kc = i >> 10;
        int n0 = wN * 64 + nj * 16, k0 = kc * 32 + ks * 16;
        uint4 h, l;
        uint32_t* hp = (uint32_t*)&h;
        uint32_t* lp = (uint32_t*)&l;
        #pragma unroll
        for (int j = 0; j < 4; j++) {
            int n = n0 + ((j >> 1) << 3) + (lane >> 2);
            int k = k0 + ((j & 1) << 3) + (lane & 3) * 2;
            float s = g1[n] * RS_;
            hp[j] = fold2(W1[(size_t)n * INCH + C2_ + k], W1[(size_t)n * INCH + C2_ + k + 1], s, lp[j]);
        }
        g_W1bp_hi[i] = h;
        g_W1bp_lo[i] = l;
    }
    for (int i = tt; i < 8192; i += nt) {
        int lane = i & 31, nj = (i >> 5) & 1, wN = (i >> 6) & 3, ks = (i >> 8) & 1,
            kc = (i >> 9) & 7, nb = (i >> 12) & 1;
        int n0 = nb * 128 + wN * 32 + nj * 16, k0 = kc * 32 + ks * 16;
        uint4 h, l;
        uint32_t* hp = (uint32_t*)&h;
        uint32_t* lp = (uint32_t*)&l;
        #pragma unroll
        for (int j = 0; j < 4; j++) {
            int n = n0 + ((j >> 1) << 3) + (lane >> 2);
            int k = k0 + ((j & 1) << 3) + (lane & 3) * 2;
            float s = g1[n] * RS_;
            hp[j] = fold2(W1[(size_t)n * INCH + k], W1[(size_t)n * INCH + k + 1], s, lp[j]);
        }
        g_W1ap_hi[i] = h;
        g_W1ap_lo[i] = l;
    }
    for (int i = tt; i < O1_; i += nt) g_b1eff[i] = g1[i] * RS_ * b1[i] + be1[i];
    for (int i = tt; i < O2_; i += nt) g_b2eff[i] = g2[i] * RS_ * b2[i] + be2[i];
}

// ============================================================
extern "C" void kernel_launch(void* const* d_in, const int* in_sizes, int n_in,
                              void* d_out, int out_size) {
    const float* xyz1   = (const float*)d_in[0];
    const float* xyz2   = (const float*)d_in[1];
    const float* feats1 = (const float*)d_in[2];
    const float* feats2 = (const float*)d_in[3];
    const float* W1     = (const float*)d_in[4];
    const float* b1     = (const float*)d_in[5];
    const float* g1     = (const float*)d_in[6];
    const float* be1    = (const float*)d_in[7];
    const float* W2     = (const float*)d_in[8];
    const float* b2     = (const float*)d_in[9];
    const float* g2     = (const float*)d_in[10];
    const float* be2    = (const float*)d_in[11];
    float* out = (float*)d_out;

    cudaFuncSetAttribute(fused12_kernel, cudaFuncAttributeMaxDynamicSharedMemorySize, FSM_BYTES);

    prepsplit_kernel<<<TS1_BLKS + TS2_BLKS + PACK_BLKS, 256>>>(
        feats1, feats2, W1, b1, g1, be1, W2, b2, g2, be2);            // idx 0
    knnseg_kernel<<<dim3(N1_ / 256, SEG, B_), 256>>>(xyz1, xyz2);     // idx 1
    knnmerge_kernel<<<(B_ * N1_) / 256, 256>>>();                     // idx 2
    gemmP_kernel<<<dim3(N2_ / 64, O1_ / 128, B_), 256>>>();           // idx 3 -> ncu
    fused12_kernel<<<dim3(N1_ / 64, B_), 256, FSM_BYTES>>>(out);      // idx 4
}